// round 12
// baseline (speedup 1.0000x reference)
#include <cuda_runtime.h>

// ---------------------------------------------------------------------------
// SparseCoupleDeConvTest: stride-2 sparse conv3d (CIN=32 -> COUT=64, K=3)
// followed by its exact adjoint, masked to the sparse coords, channel-major.
//
// Weight-stationary implicit GEMM: incidences (mid voxel, point) are binned by
// kernel offset t; per bucket, each warp keeps its weight slice in registers
// and streams pairs (1 coalesced gather + broadcast LDS + 32 FFMA2 + atomic).
// ---------------------------------------------------------------------------

typedef unsigned long long ull;

namespace {
constexpr int Dz = 41, Hy = 159, Wx = 159;
constexpr int OD = 20, OH = 79, OW = 79;
constexpr int CIN = 32, COUT = 64;
constexpr int B = 2;
constexpr int NVOX = B * Dz * Hy * Wx;          // 2,073,042
constexpr int NMID = B * OD * OH * OW;          // 249,640
constexpr int NWQ  = 27 * 16 * 32;              // 13,824 ulonglong2 per tensor
constexpr int MAXB = 150016;                    // max pairs per bucket (<= npts)
constexpr int BPT  = 24;                        // blocks per bucket in gemm kernels
}

// Scratch (allocation-free: __device__ globals)
__device__ int        g_idxmap[NVOX];                   // voxel -> point id or -1
__device__ float      g_mid[(size_t)NMID * COUT];       // dense mid activations (~64 MB)
__device__ float      g_acc[(size_t)MAXB * 32];         // per-point output accumulators
__device__ ulonglong2 g_w1q[NWQ];                       // w1: [t][i2][lane] cout-pair granules
__device__ ulonglong2 g_w2q[NWQ];                       // w2: [k][jp2][lane=cin] j-granules
__device__ int        g_cnt1[27];                       // bucket counts, stage 1
__device__ int        g_cnt2[27];                       // bucket counts, stage 2
__device__ int2       g_bin1[27 * (size_t)MAXB];        // (mid voxel, point)
__device__ int2       g_bin2[27 * (size_t)MAXB];        // (mid voxel, point)

// ---- packed fp32x2 helpers (sm_103a) --------------------------------------
__device__ __forceinline__ ull ffma2(ull a, ull b, ull c) {
    ull d;
    asm("fma.rn.f32x2 %0, %1, %2, %3;" : "=l"(d) : "l"(a), "l"(b), "l"(c));
    return d;
}
__device__ __forceinline__ ull fadd2(ull a, ull b) {
    ull d;
    asm("add.rn.f32x2 %0, %1, %2;" : "=l"(d) : "l"(a), "l"(b));
    return d;
}
__device__ __forceinline__ ull pack2(float x, float y) {
    ull r;
    asm("mov.b64 %0, {%1, %2};" : "=l"(r) : "f"(x), "f"(y));
    return r;
}
__device__ __forceinline__ float2 unpack2(ull a) {
    float2 r;
    asm("mov.b64 {%0, %1}, %2;" : "=f"(r.x), "=f"(r.y) : "l"(a));
    return r;
}

// ---- launch #1: zero everything -------------------------------------------
__global__ void zero_fill_kernel(float4* __restrict__ out, int n4, int nacc4) {
    int i = blockIdx.x * blockDim.x + threadIdx.x;
    int stride = gridDim.x * blockDim.x;
    float4 z = make_float4(0.f, 0.f, 0.f, 0.f);
    for (int j = i; j < n4; j += stride) out[j] = z;
    float4* midv = (float4*)g_mid;
    for (int j = i; j < NMID * (COUT / 4); j += stride) midv[j] = z;
    float4* accv = (float4*)g_acc;
    for (int j = i; j < nacc4; j += stride) accv[j] = z;
    for (int j = i; j < NVOX; j += stride) g_idxmap[j] = -1;
    if (i < 27) { g_cnt1[i] = 0; g_cnt2[i] = 0; }
}

// ---- launch #2: scatter point ids ------------------------------------------
__global__ void scatter_pts_kernel(const int* __restrict__ coors, int npts) {
    int n = blockIdx.x * blockDim.x + threadIdx.x;
    if (n >= npts) return;
    int4 c = ((const int4*)coors)[n];      // (b, z, y, x)
    g_idxmap[((c.x * Dz + c.y) * Hy + c.z) * Wx + c.w] = n;
}

// ---- launch #3: repack both weight tensors ---------------------------------
// w layout (K,K,K,CIN,COUT): flat = t*2048 + i*64 + j
__global__ void build_wq_kernel(const float* __restrict__ w1,
                                const float* __restrict__ w2) {
    int id = blockIdx.x * blockDim.x + threadIdx.x;
    if (id < NWQ) {
        int lane = id & 31, i2 = (id >> 5) & 15, t = id >> 9;
        float2 a = *(const float2*)(w1 + t * 2048 + (2 * i2)     * 64 + 2 * lane);
        float2 b = *(const float2*)(w1 + t * 2048 + (2 * i2 + 1) * 64 + 2 * lane);
        ulonglong2 v;
        v.x = pack2(a.x, a.y);
        v.y = pack2(b.x, b.y);
        g_w1q[id] = v;
    } else if (id < 2 * NWQ) {
        int id2 = id - NWQ;
        int lane = id2 & 31, jp2 = (id2 >> 5) & 15, k = id2 >> 9;
        float4 f = *(const float4*)(w2 + k * 2048 + lane * 64 + 4 * jp2);
        ulonglong2 v;
        v.x = pack2(f.x, f.y);
        v.y = pack2(f.z, f.w);
        g_w2q[id2] = v;
    }
}

// ---- launch #4: probe + bin stage-1 incidences by tap t ---------------------
// One warp per mid voxel; lane < 27 probes tap = lane (VALID conv, in bounds).
__global__ __launch_bounds__(256) void bin1_kernel() {
    int gw   = (blockIdx.x * 256 + threadIdx.x) >> 5;
    int lane = threadIdx.x & 31;
    if (gw >= NMID || lane >= 27) return;

    int tmp = gw;
    int ox = tmp % OW; tmp /= OW;
    int oy = tmp % OH; tmp /= OH;
    int oz = tmp % OD;
    int b  = tmp / OD;

    int tz = lane / 9;
    int tr = lane - tz * 9;
    int ty = tr / 3;
    int tx = tr - ty * 3;
    int q = g_idxmap[((b * Dz + (2 * oz + tz)) * Hy + (2 * oy + ty)) * Wx + (2 * ox + tx)];
    if (q >= 0) {
        int pos = atomicAdd(&g_cnt1[lane], 1);
        g_bin1[(size_t)lane * MAXB + pos] = make_int2(gw, q);
    }
}

// ---- launch #5: bin stage-2 incidences by tap k -----------------------------
// Candidate mid coords per dim: 2o + k = v, k in {0,1,2}, 0 <= o < O.
__device__ __forceinline__ int cands(int v, int O, int* os, int* ks) {
    if (v & 1) { os[0] = v >> 1; ks[0] = 1; return 1; }
    int n = 0, h = v >> 1;
    if (h < O) { os[n] = h;     ks[n] = 0; n++; }
    if (h > 0) { os[n] = h - 1; ks[n] = 2; n++; }
    return n;
}

__global__ void bin2_kernel(const int* __restrict__ coors, int npts) {
    int n = blockIdx.x * blockDim.x + threadIdx.x;
    if (n >= npts) return;
    int4 c = ((const int4*)coors)[n];
    int oz[2], kz[2], oy[2], ky[2], ox[2], kx[2];
    int na = cands(c.y, OD, oz, kz);
    int nb = cands(c.z, OH, oy, ky);
    int nc = cands(c.w, OW, ox, kx);
    for (int a = 0; a < na; a++)
        for (int bb = 0; bb < nb; bb++)
            for (int cc = 0; cc < nc; cc++) {
                int mo = ((c.x * OD + oz[a]) * OH + oy[bb]) * OW + ox[cc];
                int k  = (kz[a] * 3 + ky[bb]) * 3 + kx[cc];
                int pos = atomicAdd(&g_cnt2[k], 1);
                g_bin2[(size_t)k * MAXB + pos] = make_int2(mo, n);
            }
}

// ---- launch #6: stage-1 GEMM (weight-stationary) ----------------------------
// Block handles bucket t = blockIdx.x % 27. Lane holds w1[t][:, 2l:2l+2] in
// 32 ull registers. Per pair: coalesced feature gather -> smem broadcast ->
// 32 FFMA2 -> coalesced float2 atomic accumulate into g_mid.
__global__ __launch_bounds__(256, 2) void gemm1_kernel(const float* __restrict__ features) {
    __shared__ __align__(16) ull sfeat[8][2][4][32];
    int t     = blockIdx.x % 27;
    int chunk = blockIdx.x / 27;
    int w     = threadIdx.x >> 5;
    int lane  = threadIdx.x & 31;
    int nt = g_cnt1[t];

    ull W[32];
    {
        const ulonglong2* wq = g_w1q + t * 512 + lane;
#pragma unroll
        for (int m = 0; m < 16; m++) {
            ulonglong2 v = __ldg(wq + m * 32);
            W[2 * m] = v.x; W[2 * m + 1] = v.y;
        }
    }
    const int2* bin = g_bin1 + (size_t)t * MAXB;
    int buf = 0;
    for (int base = (chunk * 8 + w) * 4; base < nt; base += BPT * 8 * 4) {
        int m = nt - base; if (m > 4) m = 4;
        int2 pr[4]; float f[4];
#pragma unroll
        for (int j = 0; j < 4; j++)
            if (j < m) {
                pr[j] = __ldg(bin + base + j);
                f[j]  = __ldg(features + (size_t)pr[j].y * CIN + lane);  // MLP=4
            }
        __syncwarp();
#pragma unroll
        for (int j = 0; j < 4; j++)
            if (j < m) sfeat[w][buf][j][lane] = pack2(f[j], f[j]);
        __syncwarp();
#pragma unroll
        for (int j = 0; j < 4; j++)
            if (j < m) {
                const ulonglong2* fq = (const ulonglong2*)sfeat[w][buf][j];
                ull a0 = 0ull, a1 = 0ull;
#pragma unroll
                for (int m2 = 0; m2 < 16; m2++) {
                    ulonglong2 fv = fq[m2];
                    a0 = ffma2(fv.x, W[2 * m2],     a0);
                    a1 = ffma2(fv.y, W[2 * m2 + 1], a1);
                }
                float2 r = unpack2(fadd2(a0, a1));
                float* dst = g_mid + (size_t)pr[j].x * COUT + 2 * lane;
                atomicAdd(dst,     r.x);
                atomicAdd(dst + 1, r.y);
            }
        buf ^= 1;
    }
}

// ---- launch #7: stage-2 GEMM (weight-stationary adjoint) --------------------
// Lane = input channel i; holds w2[k][i][0..63] in 32 ull registers.
// Per pair: coalesced mid-row gather (256B) -> smem broadcast -> 32 FFMA2 ->
// fold -> coalesced scalar atomic into g_acc[point][i].
__global__ __launch_bounds__(256, 2) void gemm2_kernel() {
    __shared__ __align__(16) ull srow[8][2][4][32];
    int k     = blockIdx.x % 27;
    int chunk = blockIdx.x / 27;
    int w     = threadIdx.x >> 5;
    int lane  = threadIdx.x & 31;
    int nt = g_cnt2[k];

    ull W[32];
    {
        const ulonglong2* wq = g_w2q + k * 512 + lane;
#pragma unroll
        for (int m = 0; m < 16; m++) {
            ulonglong2 v = __ldg(wq + m * 32);
            W[2 * m] = v.x; W[2 * m + 1] = v.y;
        }
    }
    const int2* bin = g_bin2 + (size_t)k * MAXB;
    const ull* midu = (const ull*)g_mid;
    int buf = 0;
    for (int base = (chunk * 8 + w) * 4; base < nt; base += BPT * 8 * 4) {
        int m = nt - base; if (m > 4) m = 4;
        int2 pr[4]; ull mv[4];
#pragma unroll
        for (int j = 0; j < 4; j++)
            if (j < m) {
                pr[j] = __ldg(bin + base + j);
                mv[j] = __ldg(midu + (size_t)pr[j].x * 32 + lane);      // MLP=4
            }
        __syncwarp();
#pragma unroll
        for (int j = 0; j < 4; j++)
            if (j < m) srow[w][buf][j][lane] = mv[j];
        __syncwarp();
#pragma unroll
        for (int j = 0; j < 4; j++)
            if (j < m) {
                const ulonglong2* mq = (const ulonglong2*)srow[w][buf][j];
                ull a0 = 0ull, a1 = 0ull;
#pragma unroll
                for (int m2 = 0; m2 < 16; m2++) {
                    ulonglong2 fv = mq[m2];
                    a0 = ffma2(fv.x, W[2 * m2],     a0);
                    a1 = ffma2(fv.y, W[2 * m2 + 1], a1);
                }
                float2 r = unpack2(fadd2(a0, a1));
                atomicAdd(g_acc + (size_t)pr[j].y * 32 + lane, r.x + r.y);
            }
        buf ^= 1;
    }
}

// ---- launch #8: scatter accumulators to channel-major output ----------------
__global__ void scatter_out_kernel(const int* __restrict__ coors, int npts,
                                   float* __restrict__ out) {
    int gw   = (blockIdx.x * 256 + threadIdx.x) >> 5;
    int lane = threadIdx.x & 31;
    if (gw >= npts) return;
    int4 c = ((const int4*)coors)[gw];
    float v = g_acc[(size_t)gw * 32 + lane];
    size_t oidx = (((size_t)(c.x * CIN + lane)) * Dz + c.y) * ((size_t)Hy * Wx)
                + (size_t)c.z * Wx + c.w;
    out[oidx] = v;
}

// ---------------------------------------------------------------------------

extern "C" void kernel_launch(void* const* d_in, const int* in_sizes, int n_in,
                              void* d_out, int out_size) {
    if (n_in < 4) return;
    const float* features = (const float*)d_in[0];
    const int*   coors    = (const int*)d_in[1];
    const float* w1       = (const float*)d_in[n_in - 2];
    const float* w2       = (const float*)d_in[n_in - 1];
    float* out = (float*)d_out;
    int npts = in_sizes[1] / 4;

    int n4    = out_size / 4;
    int nacc4 = (npts * 32 + 3) / 4;

    zero_fill_kernel<<<8192, 256>>>((float4*)out, n4, nacc4);           // #1
    scatter_pts_kernel<<<(npts + 255) / 256, 256>>>(coors, npts);       // #2
    build_wq_kernel<<<(2 * NWQ + 255) / 256, 256>>>(w1, w2);            // #3
    bin1_kernel<<<(NMID + 7) / 8, 256>>>();                             // #4
    bin2_kernel<<<(npts + 255) / 256, 256>>>(coors, npts);              // #5
    gemm1_kernel<<<27 * BPT, 256>>>(features);                          // #6
    gemm2_kernel<<<27 * BPT, 256>>>();                                  // #7
    scatter_out_kernel<<<(npts + 7) / 8, 256>>>(coors, npts, out);      // #8
}

// round 13
// speedup vs baseline: 1.0015x; 1.0015x over previous
#include <cuda_runtime.h>

// ---------------------------------------------------------------------------
// SparseCoupleDeConvTest: stride-2 sparse conv3d (CIN=32 -> COUT=64, K=3)
// followed by its exact adjoint, masked to the sparse coords, channel-major.
//
// Weight-stationary implicit GEMM: incidences (mid voxel, point) are binned by
// kernel offset t; per bucket, each warp keeps its weight slice in registers
// and streams pairs (1 coalesced gather + broadcast LDS + 32 FFMA2 + atomic).
// ---------------------------------------------------------------------------

typedef unsigned long long ull;

namespace {
constexpr int Dz = 41, Hy = 159, Wx = 159;
constexpr int OD = 20, OH = 79, OW = 79;
constexpr int CIN = 32, COUT = 64;
constexpr int B = 2;
constexpr int NVOX = B * Dz * Hy * Wx;          // 2,073,042
constexpr int NMID = B * OD * OH * OW;          // 249,640
constexpr int NWQ  = 27 * 16 * 32;              // 13,824 ulonglong2 per tensor
constexpr int MAXB = 150016;                    // max pairs per bucket (<= npts)
constexpr int BPT  = 24;                        // blocks per bucket in gemm kernels
}

// Scratch (allocation-free: __device__ globals)
__device__ int        g_idxmap[NVOX];                   // voxel -> point id or -1
__device__ float      g_mid[(size_t)NMID * COUT];       // dense mid activations (~64 MB)
__device__ float      g_acc[(size_t)MAXB * 32];         // per-point output accumulators
__device__ ulonglong2 g_w1q[NWQ];                       // w1: [t][i2][lane] cout-pair granules
__device__ ulonglong2 g_w2q[NWQ];                       // w2: [k][jp2][lane=cin] j-granules
__device__ int        g_cnt1[27];                       // bucket counts, stage 1
__device__ int        g_cnt2[27];                       // bucket counts, stage 2
__device__ int2       g_bin1[27 * (size_t)MAXB];        // (mid voxel, point)
__device__ int2       g_bin2[27 * (size_t)MAXB];        // (mid voxel, point)

// ---- packed fp32x2 helpers (sm_103a) --------------------------------------
__device__ __forceinline__ ull ffma2(ull a, ull b, ull c) {
    ull d;
    asm("fma.rn.f32x2 %0, %1, %2, %3;" : "=l"(d) : "l"(a), "l"(b), "l"(c));
    return d;
}
__device__ __forceinline__ ull fadd2(ull a, ull b) {
    ull d;
    asm("add.rn.f32x2 %0, %1, %2;" : "=l"(d) : "l"(a), "l"(b));
    return d;
}
__device__ __forceinline__ ull pack2(float x, float y) {
    ull r;
    asm("mov.b64 %0, {%1, %2};" : "=l"(r) : "f"(x), "f"(y));
    return r;
}
__device__ __forceinline__ float2 unpack2(ull a) {
    float2 r;
    asm("mov.b64 {%0, %1}, %2;" : "=f"(r.x), "=f"(r.y) : "l"(a));
    return r;
}

// ---- launch #1: zero everything -------------------------------------------
__global__ void zero_fill_kernel(float4* __restrict__ out, int n4, int nacc4) {
    int i = blockIdx.x * blockDim.x + threadIdx.x;
    int stride = gridDim.x * blockDim.x;
    float4 z = make_float4(0.f, 0.f, 0.f, 0.f);
    for (int j = i; j < n4; j += stride) out[j] = z;
    float4* midv = (float4*)g_mid;
    for (int j = i; j < NMID * (COUT / 4); j += stride) midv[j] = z;
    float4* accv = (float4*)g_acc;
    for (int j = i; j < nacc4; j += stride) accv[j] = z;
    for (int j = i; j < NVOX; j += stride) g_idxmap[j] = -1;
    if (i < 27) { g_cnt1[i] = 0; g_cnt2[i] = 0; }
}

// ---- launch #2: scatter point ids ------------------------------------------
__global__ void scatter_pts_kernel(const int* __restrict__ coors, int npts) {
    int n = blockIdx.x * blockDim.x + threadIdx.x;
    if (n >= npts) return;
    int4 c = ((const int4*)coors)[n];      // (b, z, y, x)
    g_idxmap[((c.x * Dz + c.y) * Hy + c.z) * Wx + c.w] = n;
}

// ---- launch #3: repack both weight tensors ---------------------------------
// w layout (K,K,K,CIN,COUT): flat = t*2048 + i*64 + j
__global__ void build_wq_kernel(const float* __restrict__ w1,
                                const float* __restrict__ w2) {
    int id = blockIdx.x * blockDim.x + threadIdx.x;
    if (id < NWQ) {
        int lane = id & 31, i2 = (id >> 5) & 15, t = id >> 9;
        float2 a = *(const float2*)(w1 + t * 2048 + (2 * i2)     * 64 + 2 * lane);
        float2 b = *(const float2*)(w1 + t * 2048 + (2 * i2 + 1) * 64 + 2 * lane);
        ulonglong2 v;
        v.x = pack2(a.x, a.y);
        v.y = pack2(b.x, b.y);
        g_w1q[id] = v;
    } else if (id < 2 * NWQ) {
        int id2 = id - NWQ;
        int lane = id2 & 31, jp2 = (id2 >> 5) & 15, k = id2 >> 9;
        float4 f = *(const float4*)(w2 + k * 2048 + lane * 64 + 4 * jp2);
        ulonglong2 v;
        v.x = pack2(f.x, f.y);
        v.y = pack2(f.z, f.w);
        g_w2q[id2] = v;
    }
}

// ---- launch #4: probe + bin stage-1 incidences by tap t ---------------------
// One warp per mid voxel; lane < 27 probes tap = lane (VALID conv, in bounds).
__global__ __launch_bounds__(256) void bin1_kernel() {
    int gw   = (blockIdx.x * 256 + threadIdx.x) >> 5;
    int lane = threadIdx.x & 31;
    if (gw >= NMID || lane >= 27) return;

    int tmp = gw;
    int ox = tmp % OW; tmp /= OW;
    int oy = tmp % OH; tmp /= OH;
    int oz = tmp % OD;
    int b  = tmp / OD;

    int tz = lane / 9;
    int tr = lane - tz * 9;
    int ty = tr / 3;
    int tx = tr - ty * 3;
    int q = g_idxmap[((b * Dz + (2 * oz + tz)) * Hy + (2 * oy + ty)) * Wx + (2 * ox + tx)];
    if (q >= 0) {
        int pos = atomicAdd(&g_cnt1[lane], 1);
        g_bin1[(size_t)lane * MAXB + pos] = make_int2(gw, q);
    }
}

// ---- launch #5: bin stage-2 incidences by tap k -----------------------------
// Candidate mid coords per dim: 2o + k = v, k in {0,1,2}, 0 <= o < O.
__device__ __forceinline__ int cands(int v, int O, int* os, int* ks) {
    if (v & 1) { os[0] = v >> 1; ks[0] = 1; return 1; }
    int n = 0, h = v >> 1;
    if (h < O) { os[n] = h;     ks[n] = 0; n++; }
    if (h > 0) { os[n] = h - 1; ks[n] = 2; n++; }
    return n;
}

__global__ void bin2_kernel(const int* __restrict__ coors, int npts) {
    int n = blockIdx.x * blockDim.x + threadIdx.x;
    if (n >= npts) return;
    int4 c = ((const int4*)coors)[n];
    int oz[2], kz[2], oy[2], ky[2], ox[2], kx[2];
    int na = cands(c.y, OD, oz, kz);
    int nb = cands(c.z, OH, oy, ky);
    int nc = cands(c.w, OW, ox, kx);
    for (int a = 0; a < na; a++)
        for (int bb = 0; bb < nb; bb++)
            for (int cc = 0; cc < nc; cc++) {
                int mo = ((c.x * OD + oz[a]) * OH + oy[bb]) * OW + ox[cc];
                int k  = (kz[a] * 3 + ky[bb]) * 3 + kx[cc];
                int pos = atomicAdd(&g_cnt2[k], 1);
                g_bin2[(size_t)k * MAXB + pos] = make_int2(mo, n);
            }
}

// ---- launch #6: stage-1 GEMM (weight-stationary) ----------------------------
// Block handles bucket t = blockIdx.x % 27. Lane holds w1[t][:, 2l:2l+2] in
// 32 ull registers. Per pair: coalesced feature gather -> smem broadcast ->
// 32 FFMA2 -> coalesced float2 atomic accumulate into g_mid.
__global__ __launch_bounds__(256, 2) void gemm1_kernel(const float* __restrict__ features) {
    __shared__ __align__(16) ull sfeat[8][2][4][32];
    int t     = blockIdx.x % 27;
    int chunk = blockIdx.x / 27;
    int w     = threadIdx.x >> 5;
    int lane  = threadIdx.x & 31;
    int nt = g_cnt1[t];

    ull W[32];
    {
        const ulonglong2* wq = g_w1q + t * 512 + lane;
#pragma unroll
        for (int m = 0; m < 16; m++) {
            ulonglong2 v = __ldg(wq + m * 32);
            W[2 * m] = v.x; W[2 * m + 1] = v.y;
        }
    }
    const int2* bin = g_bin1 + (size_t)t * MAXB;
    int buf = 0;
    for (int base = (chunk * 8 + w) * 4; base < nt; base += BPT * 8 * 4) {
        int m = nt - base; if (m > 4) m = 4;
        int2 pr[4]; float f[4];
#pragma unroll
        for (int j = 0; j < 4; j++)
            if (j < m) {
                pr[j] = __ldg(bin + base + j);
                f[j]  = __ldg(features + (size_t)pr[j].y * CIN + lane);  // MLP=4
            }
        __syncwarp();
#pragma unroll
        for (int j = 0; j < 4; j++)
            if (j < m) sfeat[w][buf][j][lane] = pack2(f[j], f[j]);
        __syncwarp();
#pragma unroll
        for (int j = 0; j < 4; j++)
            if (j < m) {
                const ulonglong2* fq = (const ulonglong2*)sfeat[w][buf][j];
                ull a0 = 0ull, a1 = 0ull;
#pragma unroll
                for (int m2 = 0; m2 < 16; m2++) {
                    ulonglong2 fv = fq[m2];
                    a0 = ffma2(fv.x, W[2 * m2],     a0);
                    a1 = ffma2(fv.y, W[2 * m2 + 1], a1);
                }
                float2 r = unpack2(fadd2(a0, a1));
                float* dst = g_mid + (size_t)pr[j].x * COUT + 2 * lane;
                atomicAdd(dst,     r.x);
                atomicAdd(dst + 1, r.y);
            }
        buf ^= 1;
    }
}

// ---- launch #7: stage-2 GEMM (weight-stationary adjoint) --------------------
// Lane = input channel i; holds w2[k][i][0..63] in 32 ull registers.
// Per pair: coalesced mid-row gather (256B) -> smem broadcast -> 32 FFMA2 ->
// fold -> coalesced scalar atomic into g_acc[point][i].
__global__ __launch_bounds__(256, 2) void gemm2_kernel() {
    __shared__ __align__(16) ull srow[8][2][4][32];
    int k     = blockIdx.x % 27;
    int chunk = blockIdx.x / 27;
    int w     = threadIdx.x >> 5;
    int lane  = threadIdx.x & 31;
    int nt = g_cnt2[k];

    ull W[32];
    {
        const ulonglong2* wq = g_w2q + k * 512 + lane;
#pragma unroll
        for (int m = 0; m < 16; m++) {
            ulonglong2 v = __ldg(wq + m * 32);
            W[2 * m] = v.x; W[2 * m + 1] = v.y;
        }
    }
    const int2* bin = g_bin2 + (size_t)k * MAXB;
    const ull* midu = (const ull*)g_mid;
    int buf = 0;
    for (int base = (chunk * 8 + w) * 4; base < nt; base += BPT * 8 * 4) {
        int m = nt - base; if (m > 4) m = 4;
        int2 pr[4]; ull mv[4];
#pragma unroll
        for (int j = 0; j < 4; j++)
            if (j < m) {
                pr[j] = __ldg(bin + base + j);
                mv[j] = __ldg(midu + (size_t)pr[j].x * 32 + lane);      // MLP=4
            }
        __syncwarp();
#pragma unroll
        for (int j = 0; j < 4; j++)
            if (j < m) srow[w][buf][j][lane] = mv[j];
        __syncwarp();
#pragma unroll
        for (int j = 0; j < 4; j++)
            if (j < m) {
                const ulonglong2* mq = (const ulonglong2*)srow[w][buf][j];
                ull a0 = 0ull, a1 = 0ull;
#pragma unroll
                for (int m2 = 0; m2 < 16; m2++) {
                    ulonglong2 fv = mq[m2];
                    a0 = ffma2(fv.x, W[2 * m2],     a0);
                    a1 = ffma2(fv.y, W[2 * m2 + 1], a1);
                }
                float2 r = unpack2(fadd2(a0, a1));
                atomicAdd(g_acc + (size_t)pr[j].y * 32 + lane, r.x + r.y);
            }
        buf ^= 1;
    }
}

// ---- launch #8: scatter accumulators to channel-major output ----------------
__global__ void scatter_out_kernel(const int* __restrict__ coors, int npts,
                                   float* __restrict__ out) {
    int gw   = (blockIdx.x * 256 + threadIdx.x) >> 5;
    int lane = threadIdx.x & 31;
    if (gw >= npts) return;
    int4 c = ((const int4*)coors)[gw];
    float v = g_acc[(size_t)gw * 32 + lane];
    size_t oidx = (((size_t)(c.x * CIN + lane)) * Dz + c.y) * ((size_t)Hy * Wx)
                + (size_t)c.z * Wx + c.w;
    out[oidx] = v;
}

// ---------------------------------------------------------------------------

extern "C" void kernel_launch(void* const* d_in, const int* in_sizes, int n_in,
                              void* d_out, int out_size) {
    if (n_in < 4) return;
    const float* features = (const float*)d_in[0];
    const int*   coors    = (const int*)d_in[1];
    const float* w1       = (const float*)d_in[n_in - 2];
    const float* w2       = (const float*)d_in[n_in - 1];
    float* out = (float*)d_out;
    int npts = in_sizes[1] / 4;

    int n4    = out_size / 4;
    int nacc4 = (npts * 32 + 3) / 4;

    zero_fill_kernel<<<8192, 256>>>((float4*)out, n4, nacc4);           // #1
    scatter_pts_kernel<<<(npts + 255) / 256, 256>>>(coors, npts);       // #2
    build_wq_kernel<<<(2 * NWQ + 255) / 256, 256>>>(w1, w2);            // #3
    bin1_kernel<<<(NMID + 7) / 8, 256>>>();                             // #4
    bin2_kernel<<<(npts + 255) / 256, 256>>>(coors, npts);              // #5
    gemm1_kernel<<<27 * BPT, 256>>>(features);                          // #6
    gemm2_kernel<<<27 * BPT, 256>>>();                                  // #7
    scatter_out_kernel<<<(npts + 7) / 8, 256>>>(coors, npts, out);      // #8
}

// round 14
// speedup vs baseline: 1.8277x; 1.8249x over previous
#include <cuda_runtime.h>

// ---------------------------------------------------------------------------
// SparseCoupleDeConvTest: stride-2 sparse conv3d (CIN=32 -> COUT=64, K=3)
// followed by its exact adjoint, masked to the sparse coords, channel-major.
//
// Point-driven incidence enumeration: for a point at v, the (mid voxel o, tap t)
// pairs with 2o+t=v (componentwise) are EXACTLY the incidences of BOTH the
// forward conv (mid[o] += feat(v) . w1[t]) and the adjoint (out(v) += mid[o] .
// w2[t]). One binned list (by tap, 27 buckets) feeds two weight-stationary
// GEMM stages where each warp keeps its 32x64 weight slice in registers.
// ---------------------------------------------------------------------------

typedef unsigned long long ull;

namespace {
constexpr int Dz = 41, Hy = 159, Wx = 159;
constexpr int OD = 20, OH = 79, OW = 79;
constexpr int CIN = 32, COUT = 64;
constexpr int NMID = 2 * OD * OH * OW;          // 249,640
constexpr int NWQ  = 27 * 16 * 32;              // 13,824 ulonglong2 per tensor
constexpr int MAXB = 40960;                     // per-bucket capacity (exp ~18.8k)
constexpr int MAXPTS = 150016;
constexpr int BPT  = 12;                        // blocks per bucket in gemm kernels
}

// Scratch (allocation-free: __device__ globals)
__device__ float      g_mid[(size_t)NMID * COUT];       // dense mid activations (~64 MB)
__device__ float      g_acc[(size_t)MAXPTS * CIN];      // per-point output accumulators
__device__ ulonglong2 g_w1q[NWQ];   // w1: [t][i2][lane] -> cout-pair granules
__device__ ulonglong2 g_w2q[NWQ];   // w2: [k][jp2][lane=cin] -> j granules
__device__ int        g_cnt[27];                        // bucket counts
__device__ int2       g_bin[27 * (size_t)MAXB];         // (mid voxel, point)

// ---- packed fp32x2 helpers (sm_103a) --------------------------------------
__device__ __forceinline__ ull ffma2(ull a, ull b, ull c) {
    ull d;
    asm("fma.rn.f32x2 %0, %1, %2, %3;" : "=l"(d) : "l"(a), "l"(b), "l"(c));
    return d;
}
__device__ __forceinline__ ull fadd2(ull a, ull b) {
    ull d;
    asm("add.rn.f32x2 %0, %1, %2;" : "=l"(d) : "l"(a), "l"(b));
    return d;
}
__device__ __forceinline__ ull pack2(float x, float y) {
    ull r;
    asm("mov.b64 %0, {%1, %2};" : "=l"(r) : "f"(x), "f"(y));
    return r;
}
__device__ __forceinline__ float2 unpack2(ull a) {
    float2 r;
    asm("mov.b64 {%0, %1}, %2;" : "=f"(r.x), "=f"(r.y) : "l"(a));
    return r;
}
// vectorized fp32 reduction (sm_90+): one REDG for an adjacent float pair
__device__ __forceinline__ void red_add2(float* p, float x, float y) {
    asm volatile("{ .reg .u64 g; cvta.to.global.u64 g, %0;"
                 "  red.global.add.v2.f32 [g], {%1, %2}; }"
                 :: "l"(p), "f"(x), "f"(y) : "memory");
}

// ---- launch #1: zero output + mid + acc + counters -------------------------
__global__ void zero_fill_kernel(float4* __restrict__ out, int n4, int nacc4) {
    int i = blockIdx.x * blockDim.x + threadIdx.x;
    int stride = gridDim.x * blockDim.x;
    float4 z = make_float4(0.f, 0.f, 0.f, 0.f);
    for (int j = i; j < n4; j += stride) out[j] = z;
    float4* midv = (float4*)g_mid;
    for (int j = i; j < NMID * (COUT / 4); j += stride) midv[j] = z;
    float4* accv = (float4*)g_acc;
    for (int j = i; j < nacc4; j += stride) accv[j] = z;
    if (i < 27) g_cnt[i] = 0;
}

// ---- launch #2: point-driven binning (block-aggregated atomics) -------------
// Candidate mid coords per dim: 2o + k = v, k in {0,1,2}, 0 <= o < O.
__device__ __forceinline__ int cands(int v, int O, int* os, int* ks) {
    if (v & 1) { os[0] = v >> 1; ks[0] = 1; return 1; }
    int n = 0, h = v >> 1;
    if (h < O) { os[n] = h;     ks[n] = 0; n++; }
    if (h > 0) { os[n] = h - 1; ks[n] = 2; n++; }
    return n;
}

__global__ __launch_bounds__(256) void bin_kernel(const int* __restrict__ coors,
                                                  int npts) {
    __shared__ int scnt[27], sbase[27];
    int tid = threadIdx.x;
    if (tid < 27) scnt[tid] = 0;
    __syncthreads();

    int n = blockIdx.x * 256 + tid;
    int4 c;
    int oz[2], kz[2], oy[2], ky[2], ox[2], kx[2];
    int na = 0, nb = 0, nc = 0;
    if (n < npts) {
        c = ((const int4*)coors)[n];
        na = cands(c.y, OD, oz, kz);
        nb = cands(c.z, OH, oy, ky);
        nc = cands(c.w, OW, ox, kx);
        for (int a = 0; a < na; a++)
            for (int bb = 0; bb < nb; bb++)
                for (int cc = 0; cc < nc; cc++)
                    atomicAdd(&scnt[(kz[a] * 3 + ky[bb]) * 3 + kx[cc]], 1);
    }
    __syncthreads();
    if (tid < 27) {
        sbase[tid] = atomicAdd(&g_cnt[tid], scnt[tid]);   // 27 globals per block
        scnt[tid] = 0;
    }
    __syncthreads();
    if (n < npts) {
        for (int a = 0; a < na; a++)
            for (int bb = 0; bb < nb; bb++)
                for (int cc = 0; cc < nc; cc++) {
                    int k  = (kz[a] * 3 + ky[bb]) * 3 + kx[cc];
                    int mo = ((c.x * OD + oz[a]) * OH + oy[bb]) * OW + ox[cc];
                    int pos = sbase[k] + atomicAdd(&scnt[k], 1);
                    if (pos < MAXB)
                        g_bin[(size_t)k * MAXB + pos] = make_int2(mo, n);
                }
    }
}

// ---- launch #3: repack both weight tensors ---------------------------------
// w layout (K,K,K,CIN,COUT): flat = t*2048 + i*64 + j
__global__ void build_wq_kernel(const float* __restrict__ w1,
                                const float* __restrict__ w2) {
    int id = blockIdx.x * blockDim.x + threadIdx.x;
    if (id < NWQ) {
        int lane = id & 31, i2 = (id >> 5) & 15, t = id >> 9;
        float2 a = *(const float2*)(w1 + t * 2048 + (2 * i2)     * 64 + 2 * lane);
        float2 b = *(const float2*)(w1 + t * 2048 + (2 * i2 + 1) * 64 + 2 * lane);
        ulonglong2 v;
        v.x = pack2(a.x, a.y);
        v.y = pack2(b.x, b.y);
        g_w1q[id] = v;
    } else if (id < 2 * NWQ) {
        int id2 = id - NWQ;
        int lane = id2 & 31, jp2 = (id2 >> 5) & 15, k = id2 >> 9;
        float4 f = *(const float4*)(w2 + k * 2048 + lane * 64 + 4 * jp2);
        ulonglong2 v;
        v.x = pack2(f.x, f.y);
        v.y = pack2(f.z, f.w);
        g_w2q[id2] = v;
    }
}

// ---- launch #4 (profiled): stage-1 GEMM, weight-stationary ------------------
// Bucket t = blockIdx.x % 27. Lane holds w1[t][:, 2l:2l+2] in 32 ull regs.
// Per pair: coalesced feature gather -> smem broadcast -> 32 FFMA2 ->
// one vector REDG (float2) into g_mid.
__global__ __launch_bounds__(256, 2) void gemm1_kernel(const float* __restrict__ features) {
    __shared__ __align__(16) ull sfeat[8][2][4][32];
    int t     = blockIdx.x % 27;
    int chunk = blockIdx.x / 27;
    int w     = threadIdx.x >> 5;
    int lane  = threadIdx.x & 31;
    int nt = g_cnt[t];

    ull W[32];
    {
        const ulonglong2* wq = g_w1q + t * 512 + lane;
#pragma unroll
        for (int m = 0; m < 16; m++) {
            ulonglong2 v = __ldg(wq + m * 32);
            W[2 * m] = v.x; W[2 * m + 1] = v.y;
        }
    }
    const int2* bin = g_bin + (size_t)t * MAXB;
    int buf = 0;
    for (int base = (chunk * 8 + w) * 4; base < nt; base += BPT * 8 * 4) {
        int m = nt - base; if (m > 4) m = 4;
        int2 pr[4]; float f[4];
#pragma unroll
        for (int j = 0; j < 4; j++)
            if (j < m) {
                pr[j] = __ldg(bin + base + j);
                f[j]  = __ldg(features + (size_t)pr[j].y * CIN + lane);  // MLP=4
            }
        __syncwarp();
#pragma unroll
        for (int j = 0; j < 4; j++)
            if (j < m) sfeat[w][buf][j][lane] = pack2(f[j], f[j]);
        __syncwarp();
#pragma unroll
        for (int j = 0; j < 4; j++)
            if (j < m) {
                const ulonglong2* fq = (const ulonglong2*)sfeat[w][buf][j];
                ull a0 = 0ull, a1 = 0ull;
#pragma unroll
                for (int m2 = 0; m2 < 16; m2++) {
                    ulonglong2 fv = fq[m2];
                    a0 = ffma2(fv.x, W[2 * m2],     a0);
                    a1 = ffma2(fv.y, W[2 * m2 + 1], a1);
                }
                float2 r = unpack2(fadd2(a0, a1));
                red_add2(g_mid + (size_t)pr[j].x * COUT + 2 * lane, r.x, r.y);
            }
        buf ^= 1;
    }
}

// ---- launch #5: stage-2 GEMM (adjoint), weight-stationary -------------------
// Lane = input channel i; holds w2[k][i][0..63] in 32 ull regs.
// Per pair: coalesced mid-row gather -> smem broadcast -> 32 FFMA2 -> fold ->
// one scalar REDG into g_acc[point][i] (coalesced across warp).
__global__ __launch_bounds__(256, 2) void gemm2_kernel() {
    __shared__ __align__(16) ull srow[8][2][4][32];
    int k     = blockIdx.x % 27;
    int chunk = blockIdx.x / 27;
    int w     = threadIdx.x >> 5;
    int lane  = threadIdx.x & 31;
    int nt = g_cnt[k];

    ull W[32];
    {
        const ulonglong2* wq = g_w2q + k * 512 + lane;
#pragma unroll
        for (int m = 0; m < 16; m++) {
            ulonglong2 v = __ldg(wq + m * 32);
            W[2 * m] = v.x; W[2 * m + 1] = v.y;
        }
    }
    const int2* bin = g_bin + (size_t)k * MAXB;
    const ull* midu = (const ull*)g_mid;
    int buf = 0;
    for (int base = (chunk * 8 + w) * 4; base < nt; base += BPT * 8 * 4) {
        int m = nt - base; if (m > 4) m = 4;
        int2 pr[4]; ull mv[4];
#pragma unroll
        for (int j = 0; j < 4; j++)
            if (j < m) {
                pr[j] = __ldg(bin + base + j);
                mv[j] = __ldg(midu + (size_t)pr[j].x * 32 + lane);      // MLP=4
            }
        __syncwarp();
#pragma unroll
        for (int j = 0; j < 4; j++)
            if (j < m) srow[w][buf][j][lane] = mv[j];
        __syncwarp();
#pragma unroll
        for (int j = 0; j < 4; j++)
            if (j < m) {
                const ulonglong2* mq = (const ulonglong2*)srow[w][buf][j];
                ull a0 = 0ull, a1 = 0ull;
#pragma unroll
                for (int m2 = 0; m2 < 16; m2++) {
                    ulonglong2 fv = mq[m2];
                    a0 = ffma2(fv.x, W[2 * m2],     a0);
                    a1 = ffma2(fv.y, W[2 * m2 + 1], a1);
                }
                float2 r = unpack2(fadd2(a0, a1));
                atomicAdd(g_acc + (size_t)pr[j].y * 32 + lane, r.x + r.y);
            }
        buf ^= 1;
    }
}

// ---- launch #6: scatter accumulators to channel-major output ----------------
__global__ void scatter_out_kernel(const int* __restrict__ coors, int npts,
                                   float* __restrict__ out) {
    int gw   = (blockIdx.x * 256 + threadIdx.x) >> 5;
    int lane = threadIdx.x & 31;
    if (gw >= npts) return;
    int4 c = ((const int4*)coors)[gw];
    float v = g_acc[(size_t)gw * 32 + lane];
    size_t oidx = (((size_t)(c.x * CIN + lane)) * Dz + c.y) * ((size_t)Hy * Wx)
                + (size_t)c.z * Wx + c.w;
    out[oidx] = v;
}

// ---------------------------------------------------------------------------

extern "C" void kernel_launch(void* const* d_in, const int* in_sizes, int n_in,
                              void* d_out, int out_size) {
    if (n_in < 4) return;
    const float* features = (const float*)d_in[0];
    const int*   coors    = (const int*)d_in[1];
    const float* w1       = (const float*)d_in[n_in - 2];
    const float* w2       = (const float*)d_in[n_in - 1];
    float* out = (float*)d_out;
    int npts = in_sizes[1] / 4;
    if (npts > MAXPTS) npts = MAXPTS;

    int n4    = out_size / 4;
    int nacc4 = (npts * 32 + 3) / 4;

    zero_fill_kernel<<<4096, 256>>>((float4*)out, n4, nacc4);           // #1
    bin_kernel<<<(npts + 255) / 256, 256>>>(coors, npts);               // #2
    build_wq_kernel<<<(2 * NWQ + 255) / 256, 256>>>(w1, w2);            // #3
    gemm1_kernel<<<27 * BPT, 256>>>(features);                          // #4 (profiled)
    gemm2_kernel<<<27 * BPT, 256>>>();                                  // #5
    scatter_out_kernel<<<(npts + 7) / 8, 256>>>(coors, npts, out);      // #6
}